// round 8
// baseline (speedup 1.0000x reference)
#include <cuda_runtime.h>

#define N_NODES 20000
#define N_EDGES 200000
#define EDIM 128
#define CE 256                 // C * E_DIM
#define MAXD 64                // bin capacity per node (Poisson(10): P(>64) ~ 1e-30)
#define NODES_PER_BLK 4        // 256 threads / 64 threads-per-node

// Scratch in __device__ globals (zero-initialized at load; g_cnt invariant:
// zero at entry of every kernel_launch call, restored by node_kernel).
__device__ int   g_cnt[N_NODES];            // per-node in-degree / scatter cursor
__device__ int   g_meta[N_NODES * MAXD];    // packed (src << 1) | pos, binned per dst
__device__ float g_scale[2][EDIM];
__device__ float g_bias[2][EDIM];

// Scatter packed edge metadata into fixed-stride per-dst bins, 4 edges/thread
// (int4 loads, 4 independent ATOMGs in flight). Block 0 also computes the
// sigmoid tables (consumed only by node_kernel, which launches after us).
__global__ void __launch_bounds__(256) scatter_kernel(
    const int* __restrict__ src, const int* __restrict__ dst,
    const int* __restrict__ pos,
    const float* __restrict__ dl, const float* __restrict__ dr,
    const float* __restrict__ lb, const float* __restrict__ rb)
{
    if (blockIdx.x == 0 && threadIdx.x < EDIM) {
        int e = threadIdx.x;
        g_scale[0][e] = 1.0f / (1.0f + __expf(-dl[e]));
        g_scale[1][e] = 1.0f / (1.0f + __expf(-dr[e]));
        g_bias[0][e]  = lb[e];
        g_bias[1][e]  = rb[e];
    }

    int t = blockIdx.x * blockDim.x + threadIdx.x;
    int e0 = t * 4;
    if (e0 >= N_EDGES) return;   // N_EDGES % 4 == 0, full int4 loads are safe

    int4 s4 = *reinterpret_cast<const int4*>(src + e0);
    int4 d4 = *reinterpret_cast<const int4*>(dst + e0);
    int4 p4 = *reinterpret_cast<const int4*>(pos + e0);

    int k0 = atomicAdd(&g_cnt[d4.x], 1);
    int k1 = atomicAdd(&g_cnt[d4.y], 1);
    int k2 = atomicAdd(&g_cnt[d4.z], 1);
    int k3 = atomicAdd(&g_cnt[d4.w], 1);

    g_meta[d4.x * MAXD + k0] = (s4.x << 1) | (p4.x != 0 ? 1 : 0);
    g_meta[d4.y * MAXD + k1] = (s4.y << 1) | (p4.y != 0 ? 1 : 0);
    g_meta[d4.z * MAXD + k2] = (s4.z << 1) | (p4.z != 0 ? 1 : 0);
    g_meta[d4.w * MAXD + k3] = (s4.w << 1) | (p4.w != 0 ? 1 : 0);
}

// Gather-reduce: 64 threads per node, each owns one float4 of the 256-float row.
// Block stages its 4 nodes' meta (256 ints, one coalesced round) + counts in
// SMEM up front, so the gather loop's address generation is LDS-latency, not
// L2-latency: chain per 4-edge round ~ LDS(29) + feat LDG(260) instead of
// meta LDG(260) + feat LDG(260). Bias folded into epilogue via in-loop pos-bit
// tally: out = (acc + nl*b0 + nr*b1) / max(deg,1).
__global__ void __launch_bounds__(256) node_kernel(const float* __restrict__ feat,
                                                   float* __restrict__ out) {
    __shared__ int s_meta[NODES_PER_BLK * MAXD];   // 1 KB
    __shared__ int s_cnt[NODES_PER_BLK];

    unsigned t      = threadIdx.x;
    unsigned node0  = blockIdx.x * NODES_PER_BLK;
    unsigned nloc   = t >> 6;                      // 0..3 node within block
    unsigned node   = node0 + nloc;
    unsigned chunk  = t & 63u;
    unsigned off    = chunk * 4u;                  // 0..252
    unsigned e      = off & (EDIM - 1);            // scale/bias repeat per channel

    // ---- stage meta + counts; reset g_cnt for next replay ----
    s_meta[t] = g_meta[node0 * MAXD + t];          // 256 ints, fully coalesced
    if (t < NODES_PER_BLK) {
        s_cnt[t] = g_cnt[node0 + t];
        g_cnt[node0 + t] = 0;
    }
    __syncthreads();

    int deg = s_cnt[nloc];
    const int* mp = &s_meta[nloc * MAXD];
    const float* fb = feat + off;

    float4 sc0 = *reinterpret_cast<const float4*>(&g_scale[0][e]);
    float4 sc1 = *reinterpret_cast<const float4*>(&g_scale[1][e]);

    float4 acc = make_float4(0.f, 0.f, 0.f, 0.f);
    int nr = 0;                                    // count of right (pos==1) edges

    int j = 0;
    for (; j + 4 <= deg; j += 4) {
        int4 m4 = *reinterpret_cast<const int4*>(mp + j);   // LDS.128, broadcast
        const float4 f0 = *reinterpret_cast<const float4*>(fb + (size_t)(m4.x >> 1) * CE);
        const float4 f1 = *reinterpret_cast<const float4*>(fb + (size_t)(m4.y >> 1) * CE);
        const float4 f2 = *reinterpret_cast<const float4*>(fb + (size_t)(m4.z >> 1) * CE);
        const float4 f3 = *reinterpret_cast<const float4*>(fb + (size_t)(m4.w >> 1) * CE);
        nr += (m4.x & 1) + (m4.y & 1) + (m4.z & 1) + (m4.w & 1);
        {
            float4 s = (m4.x & 1) ? sc1 : sc0;
            acc.x = fmaf(f0.x, s.x, acc.x); acc.y = fmaf(f0.y, s.y, acc.y);
            acc.z = fmaf(f0.z, s.z, acc.z); acc.w = fmaf(f0.w, s.w, acc.w);
        }
        {
            float4 s = (m4.y & 1) ? sc1 : sc0;
            acc.x = fmaf(f1.x, s.x, acc.x); acc.y = fmaf(f1.y, s.y, acc.y);
            acc.z = fmaf(f1.z, s.z, acc.z); acc.w = fmaf(f1.w, s.w, acc.w);
        }
        {
            float4 s = (m4.z & 1) ? sc1 : sc0;
            acc.x = fmaf(f2.x, s.x, acc.x); acc.y = fmaf(f2.y, s.y, acc.y);
            acc.z = fmaf(f2.z, s.z, acc.z); acc.w = fmaf(f2.w, s.w, acc.w);
        }
        {
            float4 s = (m4.w & 1) ? sc1 : sc0;
            acc.x = fmaf(f3.x, s.x, acc.x); acc.y = fmaf(f3.y, s.y, acc.y);
            acc.z = fmaf(f3.z, s.z, acc.z); acc.w = fmaf(f3.w, s.w, acc.w);
        }
    }
    for (; j < deg; j++) {
        int m = mp[j];
        const float4 f = *reinterpret_cast<const float4*>(fb + (size_t)(m >> 1) * CE);
        nr += (m & 1);
        float4 s = (m & 1) ? sc1 : sc0;
        acc.x = fmaf(f.x, s.x, acc.x); acc.y = fmaf(f.y, s.y, acc.y);
        acc.z = fmaf(f.z, s.z, acc.z); acc.w = fmaf(f.w, s.w, acc.w);
    }

    // epilogue: bias (nl*b0 + nr*b1) + mean
    float4 b0 = *reinterpret_cast<const float4*>(&g_bias[0][e]);
    float4 b1 = *reinterpret_cast<const float4*>(&g_bias[1][e]);
    float fnr = (float)nr;
    float fnl = (float)(deg - nr);
    float inv = 1.0f / fmaxf((float)deg, 1.0f);

    float4 r;
    r.x = (acc.x + fnl * b0.x + fnr * b1.x) * inv;
    r.y = (acc.y + fnl * b0.y + fnr * b1.y) * inv;
    r.z = (acc.z + fnl * b0.z + fnr * b1.z) * inv;
    r.w = (acc.w + fnl * b0.w + fnr * b1.w) * inv;
    *reinterpret_cast<float4*>(out + (size_t)node * CE + off) = r;
}

extern "C" void kernel_launch(void* const* d_in, const int* in_sizes, int n_in,
                              void* d_out, int out_size) {
    const float* feat = (const float*)d_in[0];
    const float* dl   = (const float*)d_in[1];
    const float* dr   = (const float*)d_in[2];
    const float* lb   = (const float*)d_in[3];
    const float* rb   = (const float*)d_in[4];
    const int*   src  = (const int*)d_in[5];
    const int*   dst  = (const int*)d_in[6];
    const int*   pos  = (const int*)d_in[7];
    float* out = (float*)d_out;

    scatter_kernel<<<(N_EDGES / 4 + 255) / 256, 256>>>(src, dst, pos, dl, dr, lb, rb);
    node_kernel<<<N_NODES / NODES_PER_BLK, 256>>>(feat, out);
}

// round 9
// speedup vs baseline: 1.6254x; 1.6254x over previous
#include <cuda_runtime.h>
#include <cuda_fp16.h>

#define N_NODES 20000
#define N_EDGES 200000
#define EDIM 128
#define CE 256                 // C * E_DIM
#define MAXD 64                // bin capacity per node (Poisson(10): P(>64) ~ 1e-30)
#define NHALF2 (N_NODES * CE / 2)   // 2,560,000 half2 elements

// Scratch in __device__ globals (zero-initialized at load; g_cnt invariant:
// zero at entry of every kernel_launch call, restored by node_kernel).
__device__ int     g_cnt[N_NODES];            // per-node in-degree / scatter cursor
__device__ int     g_meta[N_NODES * MAXD];    // packed (src << 1) | pos, binned per dst
__device__ __half2 g_feat_h[NHALF2];          // fp16 shadow of feat (10.25 MB, L2-resident)
__device__ float   g_scale[2][EDIM];
__device__ float   g_bias[2][EDIM];

// Scatter packed edge metadata into fixed-stride per-dst bins (4 edges/thread,
// int4 loads, 4 independent ATOMGs in flight), THEN grid-stride convert feat
// f32 -> fp16 shadow. Block 0 also computes the sigmoid tables. Everything here
// is consumed only by node_kernel, which launches after us.
__global__ void __launch_bounds__(256) scatter_kernel(
    const float* __restrict__ feat,
    const int* __restrict__ src, const int* __restrict__ dst,
    const int* __restrict__ pos,
    const float* __restrict__ dl, const float* __restrict__ dr,
    const float* __restrict__ lb, const float* __restrict__ rb)
{
    if (blockIdx.x == 0 && threadIdx.x < EDIM) {
        int e = threadIdx.x;
        g_scale[0][e] = 1.0f / (1.0f + __expf(-dl[e]));
        g_scale[1][e] = 1.0f / (1.0f + __expf(-dr[e]));
        g_bias[0][e]  = lb[e];
        g_bias[1][e]  = rb[e];
    }

    int t = blockIdx.x * blockDim.x + threadIdx.x;
    int e0 = t * 4;
    if (e0 < N_EDGES) {          // N_EDGES % 4 == 0, full int4 loads are safe
        int4 s4 = *reinterpret_cast<const int4*>(src + e0);
        int4 d4 = *reinterpret_cast<const int4*>(dst + e0);
        int4 p4 = *reinterpret_cast<const int4*>(pos + e0);

        int k0 = atomicAdd(&g_cnt[d4.x], 1);
        int k1 = atomicAdd(&g_cnt[d4.y], 1);
        int k2 = atomicAdd(&g_cnt[d4.z], 1);
        int k3 = atomicAdd(&g_cnt[d4.w], 1);

        g_meta[d4.x * MAXD + k0] = (s4.x << 1) | (p4.x != 0 ? 1 : 0);
        g_meta[d4.y * MAXD + k1] = (s4.y << 1) | (p4.y != 0 ? 1 : 0);
        g_meta[d4.z * MAXD + k2] = (s4.z << 1) | (p4.z != 0 ? 1 : 0);
        g_meta[d4.w * MAXD + k3] = (s4.w << 1) | (p4.w != 0 ? 1 : 0);
    }

    // fp16 shadow build: streaming, bandwidth-bound, overlaps with scatter tail
    int stride = gridDim.x * blockDim.x;
    for (int i = t; i < NHALF2; i += stride) {
        float2 f = reinterpret_cast<const float2*>(feat)[i];
        g_feat_h[i] = __floats2half2_rn(f.x, f.y);
    }
}

// Gather-reduce: 64 threads per node, each owns 4 floats (= 2 half2 = one 8B
// load per edge) of the 256-float row. Warp gather = 256B = 2 cache lines
// (half the wavefronts of the f32 version). fp32 accumulation; scale selected
// per edge; bias folded into the epilogue via pos-bit tally:
//   out = (acc + nl*b0 + nr*b1) / max(deg, 1).
__global__ void __launch_bounds__(256) node_kernel(float* __restrict__ out) {
    unsigned tid  = blockIdx.x * blockDim.x + threadIdx.x;
    unsigned node = tid >> 6;               // grid is exactly N_NODES*64 threads
    unsigned chunk = tid & 63u;
    unsigned off   = chunk * 4u;            // float offset 0..252
    unsigned e     = off & (EDIM - 1);      // scale/bias repeat per channel

    float4 sc0 = *reinterpret_cast<const float4*>(&g_scale[0][e]);
    float4 sc1 = *reinterpret_cast<const float4*>(&g_scale[1][e]);

    int deg = g_cnt[node];
    const int* mp = &g_meta[node * MAXD];
    const __half2* fb = g_feat_h + chunk * 2;   // row stride = CE/2 = 128 half2

    float4 acc = make_float4(0.f, 0.f, 0.f, 0.f);
    int nr = 0;                                 // count of right (pos==1) edges

#define GATHER4(H, IDX) \
    uint2 H = *reinterpret_cast<const uint2*>(fb + (size_t)(IDX) * (CE / 2))
#define ACCSEL(H, MBIT) do { \
    float4 s = (MBIT) ? sc1 : sc0; \
    float2 a_ = __half22float2(*reinterpret_cast<const __half2*>(&(H).x)); \
    float2 b_ = __half22float2(*reinterpret_cast<const __half2*>(&(H).y)); \
    acc.x = fmaf(a_.x, s.x, acc.x); acc.y = fmaf(a_.y, s.y, acc.y); \
    acc.z = fmaf(b_.x, s.z, acc.z); acc.w = fmaf(b_.y, s.w, acc.w); } while (0)

    int j = 0;
    for (; j + 4 <= deg; j += 4) {
        int4 m4 = *reinterpret_cast<const int4*>(mp + j);   // 16B aligned (MAXD=64)
        GATHER4(h0, m4.x >> 1);
        GATHER4(h1, m4.y >> 1);
        GATHER4(h2, m4.z >> 1);
        GATHER4(h3, m4.w >> 1);
        nr += (m4.x & 1) + (m4.y & 1) + (m4.z & 1) + (m4.w & 1);
        ACCSEL(h0, m4.x & 1);
        ACCSEL(h1, m4.y & 1);
        ACCSEL(h2, m4.z & 1);
        ACCSEL(h3, m4.w & 1);
    }
    for (; j < deg; j++) {
        int m = mp[j];
        GATHER4(h0, m >> 1);
        nr += (m & 1);
        ACCSEL(h0, m & 1);
    }
#undef GATHER4
#undef ACCSEL

    // epilogue: bias (nl*b0 + nr*b1) + mean
    float4 b0 = *reinterpret_cast<const float4*>(&g_bias[0][e]);
    float4 b1 = *reinterpret_cast<const float4*>(&g_bias[1][e]);
    float fnr = (float)nr;
    float fnl = (float)(deg - nr);
    float inv = 1.0f / fmaxf((float)deg, 1.0f);

    float4 r;
    r.x = (acc.x + fnl * b0.x + fnr * b1.x) * inv;
    r.y = (acc.y + fnl * b0.y + fnr * b1.y) * inv;
    r.z = (acc.z + fnl * b0.z + fnr * b1.z) * inv;
    r.w = (acc.w + fnl * b0.w + fnr * b1.w) * inv;
    *reinterpret_cast<float4*>(out + (size_t)node * CE + off) = r;

    // Restore g_cnt = 0 for the next graph replay. Barrier ensures both warps
    // of every node in this block have read g_cnt before any reset.
    __syncthreads();
    if (chunk == 0) g_cnt[node] = 0;
}

extern "C" void kernel_launch(void* const* d_in, const int* in_sizes, int n_in,
                              void* d_out, int out_size) {
    const float* feat = (const float*)d_in[0];
    const float* dl   = (const float*)d_in[1];
    const float* dr   = (const float*)d_in[2];
    const float* lb   = (const float*)d_in[3];
    const float* rb   = (const float*)d_in[4];
    const int*   src  = (const int*)d_in[5];
    const int*   dst  = (const int*)d_in[6];
    const int*   pos  = (const int*)d_in[7];
    float* out = (float*)d_out;

    scatter_kernel<<<(N_EDGES / 4 + 255) / 256, 256>>>(feat, src, dst, pos, dl, dr, lb, rb);
    node_kernel<<<N_NODES * 64 / 256, 256>>>(out);
}

// round 10
// speedup vs baseline: 1.7749x; 1.0920x over previous
#include <cuda_runtime.h>
#include <cuda_fp16.h>

#define N_NODES 20000
#define N_EDGES 200000
#define EDIM 128
#define CE 256                 // C * E_DIM
#define MAXDS 48               // per-side bin capacity (Poisson(5)/side: P(>48) ~ 1e-30)
#define NHALF2 (N_NODES * CE / 2)   // 2,560,000 half2 elements
#define SCATTER_THREADS (N_EDGES / 4)
#define CONV_BLOCKS 1280

// Scratch in __device__ globals (zero-initialized at load; g_cnt invariant:
// zero at entry of every kernel_launch call, restored by node_kernel).
__device__ int     g_cnt[N_NODES];              // packed: lo16 = n_left, hi16 = n_right
__device__ int     g_meta_l[N_NODES * MAXDS];   // src indices of left (pos==0) edges
__device__ int     g_meta_r[N_NODES * MAXDS];   // src indices of right (pos==1) edges
__device__ __half2 g_feat_h[NHALF2];            // fp16 shadow of feat (10.25 MB, L2-resident)
__device__ float   g_scale[2][EDIM];
__device__ float   g_bias[2][EDIM];

// One launch does: sigmoid tables (block 0), per-pos bin scatter (first 50K
// threads), and the f32->fp16 feat shadow build (ALL 327K threads grid-stride,
// properly parallelized this time). All outputs consumed only by node_kernel.
__global__ void __launch_bounds__(256) scatter_kernel(
    const float* __restrict__ feat,
    const int* __restrict__ src, const int* __restrict__ dst,
    const int* __restrict__ pos,
    const float* __restrict__ dl, const float* __restrict__ dr,
    const float* __restrict__ lb, const float* __restrict__ rb)
{
    if (blockIdx.x == 0 && threadIdx.x < EDIM) {
        int e = threadIdx.x;
        g_scale[0][e] = 1.0f / (1.0f + __expf(-dl[e]));
        g_scale[1][e] = 1.0f / (1.0f + __expf(-dr[e]));
        g_bias[0][e]  = lb[e];
        g_bias[1][e]  = rb[e];
    }

    int t = blockIdx.x * blockDim.x + threadIdx.x;

    if (t < SCATTER_THREADS) {     // N_EDGES % 4 == 0, full int4 loads are safe
        int e0 = t * 4;
        int4 s4 = *reinterpret_cast<const int4*>(src + e0);
        int4 d4 = *reinterpret_cast<const int4*>(dst + e0);
        int4 p4 = *reinterpret_cast<const int4*>(pos + e0);

        #pragma unroll
        for (int k = 0; k < 4; k++) {
            int s = (&s4.x)[k];
            int d = (&d4.x)[k];
            bool right = ((&p4.x)[k] != 0);
            int old = atomicAdd(&g_cnt[d], right ? 0x10000 : 1);
            if (right) g_meta_r[d * MAXDS + (old >> 16)]    = s;
            else       g_meta_l[d * MAXDS + (old & 0xFFFF)] = s;
        }
    }

    // fp16 shadow: each iter converts one float4 -> 2 half2 (8B store)
    int stride = gridDim.x * blockDim.x;
    for (int i = t; i < NHALF2 / 2; i += stride) {
        float4 f = reinterpret_cast<const float4*>(feat)[i];
        __half2 h0 = __floats2half2_rn(f.x, f.y);
        __half2 h1 = __floats2half2_rn(f.z, f.w);
        uint2 u;
        u.x = *reinterpret_cast<unsigned*>(&h0);
        u.y = *reinterpret_cast<unsigned*>(&h1);
        reinterpret_cast<uint2*>(g_feat_h)[i] = u;
    }
}

// Convert a half2 (in a uint32) to fp32 pair and accumulate into a packed
// f32x2 accumulator with ONE add.rn.f32x2 (sm_103a packed fp32 SIMD).
__device__ __forceinline__ void acc_h2(unsigned long long& acc, unsigned h) {
    asm("{\n\t"
        ".reg .b16 lo, hi;\n\t"
        ".reg .f32 fl, fh;\n\t"
        ".reg .b64 t;\n\t"
        "mov.b32 {lo, hi}, %1;\n\t"
        "cvt.f32.f16 fl, lo;\n\t"
        "cvt.f32.f16 fh, hi;\n\t"
        "mov.b64 t, {fl, fh};\n\t"
        "add.rn.f32x2 %0, %0, t;\n\t"
        "}" : "+l"(acc) : "r"(h));
}

__device__ __forceinline__ float2 unpack_f32x2(unsigned long long v) {
    float2 r;
    asm("mov.b64 {%0, %1}, %2;" : "=f"(r.x), "=f"(r.y) : "l"(v));
    return r;
}

// Gather-reduce: 64 threads per node, each owns 4 floats (one 8B fp16 load per
// edge). Select-free raw sums per side (left/right chains interleaved for MLP);
// per edge: 1 addr IMAD + LDG.64 + 2 F2F + 2 packed FADD2. Scale+bias applied
// once in the epilogue: out = (accL*sc0 + accR*sc1 + nl*b0 + nr*b1)/max(deg,1).
__global__ void __launch_bounds__(256) node_kernel(float* __restrict__ out) {
    unsigned tid  = blockIdx.x * blockDim.x + threadIdx.x;
    unsigned node = tid >> 6;               // grid is exactly N_NODES*64 threads
    unsigned chunk = tid & 63u;
    unsigned off   = chunk * 4u;            // float offset 0..252
    unsigned e     = off & (EDIM - 1);      // scale/bias repeat per channel

    int cnt = g_cnt[node];
    int nl = cnt & 0xFFFF;
    int nr = cnt >> 16;

    const int* mpl = &g_meta_l[node * MAXDS];
    const int* mpr = &g_meta_r[node * MAXDS];
    const __half2* fb = g_feat_h + chunk * 2;   // row stride = CE/2 = 128 half2

    unsigned long long aL0 = 0, aL1 = 0, aR0 = 0, aR1 = 0;

    int nmin = min(nl, nr);
    int j = 0;
    for (; j + 2 <= nmin; j += 2) {             // 4 independent loads in flight
        int sl0 = __ldg(mpl + j), sl1 = __ldg(mpl + j + 1);
        int sr0 = __ldg(mpr + j), sr1 = __ldg(mpr + j + 1);
        uint2 hl0 = *reinterpret_cast<const uint2*>(fb + (size_t)sl0 * (CE / 2));
        uint2 hl1 = *reinterpret_cast<const uint2*>(fb + (size_t)sl1 * (CE / 2));
        uint2 hr0 = *reinterpret_cast<const uint2*>(fb + (size_t)sr0 * (CE / 2));
        uint2 hr1 = *reinterpret_cast<const uint2*>(fb + (size_t)sr1 * (CE / 2));
        acc_h2(aL0, hl0.x); acc_h2(aL1, hl0.y);
        acc_h2(aL0, hl1.x); acc_h2(aL1, hl1.y);
        acc_h2(aR0, hr0.x); acc_h2(aR1, hr0.y);
        acc_h2(aR0, hr1.x); acc_h2(aR1, hr1.y);
    }
    for (; j < nmin; j++) {
        int sl = __ldg(mpl + j), sr = __ldg(mpr + j);
        uint2 hl = *reinterpret_cast<const uint2*>(fb + (size_t)sl * (CE / 2));
        uint2 hr = *reinterpret_cast<const uint2*>(fb + (size_t)sr * (CE / 2));
        acc_h2(aL0, hl.x); acc_h2(aL1, hl.y);
        acc_h2(aR0, hr.x); acc_h2(aR1, hr.y);
    }
    for (int k = nmin; k < nl; k++) {
        int sl = __ldg(mpl + k);
        uint2 hl = *reinterpret_cast<const uint2*>(fb + (size_t)sl * (CE / 2));
        acc_h2(aL0, hl.x); acc_h2(aL1, hl.y);
    }
    for (int k = nmin; k < nr; k++) {
        int sr = __ldg(mpr + k);
        uint2 hr = *reinterpret_cast<const uint2*>(fb + (size_t)sr * (CE / 2));
        acc_h2(aR0, hr.x); acc_h2(aR1, hr.y);
    }

    // epilogue: scale + bias + mean (fp32)
    float2 l01 = unpack_f32x2(aL0), l23 = unpack_f32x2(aL1);
    float2 r01 = unpack_f32x2(aR0), r23 = unpack_f32x2(aR1);
    float4 sc0 = *reinterpret_cast<const float4*>(&g_scale[0][e]);
    float4 sc1 = *reinterpret_cast<const float4*>(&g_scale[1][e]);
    float4 b0  = *reinterpret_cast<const float4*>(&g_bias[0][e]);
    float4 b1  = *reinterpret_cast<const float4*>(&g_bias[1][e]);
    float fnl = (float)nl, fnr = (float)nr;
    float inv = 1.0f / fmaxf(fnl + fnr, 1.0f);

    float4 r;
    r.x = (l01.x * sc0.x + r01.x * sc1.x + fnl * b0.x + fnr * b1.x) * inv;
    r.y = (l01.y * sc0.y + r01.y * sc1.y + fnl * b0.y + fnr * b1.y) * inv;
    r.z = (l23.x * sc0.z + r23.x * sc1.z + fnl * b0.z + fnr * b1.z) * inv;
    r.w = (l23.y * sc0.w + r23.y * sc1.w + fnl * b0.w + fnr * b1.w) * inv;
    *reinterpret_cast<float4*>(out + (size_t)node * CE + off) = r;

    // Restore g_cnt = 0 for the next graph replay. Barrier ensures both warps
    // of every node in this block have read g_cnt before any reset.
    __syncthreads();
    if (chunk == 0) g_cnt[node] = 0;
}

extern "C" void kernel_launch(void* const* d_in, const int* in_sizes, int n_in,
                              void* d_out, int out_size) {
    const float* feat = (const float*)d_in[0];
    const float* dl   = (const float*)d_in[1];
    const float* dr   = (const float*)d_in[2];
    const float* lb   = (const float*)d_in[3];
    const float* rb   = (const float*)d_in[4];
    const int*   src  = (const int*)d_in[5];
    const int*   dst  = (const int*)d_in[6];
    const int*   pos  = (const int*)d_in[7];
    float* out = (float*)d_out;

    scatter_kernel<<<CONV_BLOCKS, 256>>>(feat, src, dst, pos, dl, dr, lb, rb);
    node_kernel<<<N_NODES * 64 / 256, 256>>>(out);
}